// round 14
// baseline (speedup 1.0000x reference)
#include <cuda_runtime.h>
#include <cuda_bf16.h>
#include <cstdint>

#define NN 50000
#define FF 64
#define HH 128
#define GG 512
#define BN_EPSF 1e-3f
#define NTILES ((NN + 127) / 128)   // 391
#define PAD 96                       // max supported degree per node

// ---------------- scratch (device globals; no dynamic alloc allowed) ----------
static __device__ float    g_y[NN * HH];   // pre-GEMM output (pre-BN)
static __device__ float    g_a[NN * HH];   // A = h @ (W1-W2) + b_cn  (fp32)
static __device__ unsigned g_bh[NN * 64];  // B = h @ W2 as bf16x2 pairs
static __device__ float    g_p[GG * HH];   // pooled per-graph sums
static __device__ float    g_y2[GG * HH];  // post-GEMM output (pre-BN)
static __device__ float    g_sum1[HH];
static __device__ float    g_sumsq1[HH];
static __device__ double   g_sum2[HH];
static __device__ double   g_sumsq2[HH];
// padded adjacency
static __device__ int      g_cnt[NN];          // degree (atomic cursor)
static __device__ int      g_adj[NN * PAD];    // dst per edge, grouped by src

// ---------------- PTX helpers (sm_80-era: ldmatrix + mma.sync) ---------------
__device__ __forceinline__ uint32_t smem_u32(const void* p) {
    uint32_t a;
    asm("{ .reg .u64 t; cvta.to.shared.u64 t, %1; cvt.u32.u64 %0, t; }"
        : "=r"(a) : "l"(p));
    return a;
}

#define LDSM_X4(r0, r1, r2, r3, addr)                                          \
    asm volatile("ldmatrix.sync.aligned.m8n8.x4.shared.b16 {%0,%1,%2,%3}, [%4];" \
                 : "=r"(r0), "=r"(r1), "=r"(r2), "=r"(r3) : "r"(addr))

#define LDSM_X2T(r0, r1, addr)                                                 \
    asm volatile("ldmatrix.sync.aligned.m8n8.x2.trans.shared.b16 {%0,%1}, [%2];" \
                 : "=r"(r0), "=r"(r1) : "r"(addr))

#define MMA16816(d0, d1, d2, d3, a0, a1, a2, a3, b0, b1)                       \
    asm volatile("mma.sync.aligned.m16n8k16.row.col.f32.bf16.bf16.f32 "        \
                 "{%0,%1,%2,%3}, {%4,%5,%6,%7}, {%8,%9}, {%0,%1,%2,%3};"       \
                 : "+f"(d0), "+f"(d1), "+f"(d2), "+f"(d3)                      \
                 : "r"(a0), "r"(a1), "r"(a2), "r"(a3), "r"(b0), "r"(b1))

__device__ __forceinline__ void split_pack(float a0, float a1,
                                           unsigned& hp, unsigned& lp) {
    asm("cvt.rn.bf16x2.f32 %0, %1, %2;" : "=r"(hp) : "f"(a1), "f"(a0));
    float h0 = __uint_as_float(hp << 16);
    float h1 = __uint_as_float(hp & 0xffff0000u);
    float l0 = a0 - h0, l1 = a1 - h1;
    asm("cvt.rn.bf16x2.f32 %0, %1, %2;" : "=r"(lp) : "f"(l1), "f"(l0));
}

// ---------------- zero kernels (split: k1 must be launch #4 for ncu) ---------
__global__ void kzero_p() {
    int t = blockIdx.x * blockDim.x + threadIdx.x;
    if (t < GG * HH) g_p[t] = 0.f;
    if (t < HH) {
        g_sum1[t] = 0.f; g_sumsq1[t] = 0.f;
        g_sum2[t] = 0.0; g_sumsq2[t] = 0.0;
    }
}
__global__ void kzero_cnt() {
    int t = blockIdx.x * blockDim.x + threadIdx.x;
    if (t < NN) g_cnt[t] = 0;
}

// ---------------- adjacency build: single pass, padded slots -----------------
__global__ void kscat2(const int* __restrict__ src, const int* __restrict__ dst,
                       int E) {
    int base = (blockIdx.x * blockDim.x + threadIdx.x) * 8;
#pragma unroll
    for (int u = 0; u < 8; u++) {
        int e = base + u;
        if (e < E) {
            int s = __ldg(src + e);
            int pos = atomicAdd(&g_cnt[s], 1);
            if (pos < PAD) g_adj[s * PAD + pos] = __ldg(dst + e);
        }
    }
}

// ---------------- K1: y = x @ w_pre + b_pre ; split-K over 2 thread halves ---
// 256 threads: (col = t&127, khalf = t>>7). Each holds 32 w regs.
#define K1_ROWS 44
__global__ void __launch_bounds__(256) k1(const float* __restrict__ x,
                                          const float* __restrict__ wpre,
                                          const float* __restrict__ bpre) {
    __shared__ __align__(16) float xs[8 * FF];
    __shared__ float part[8 * 128];
    const int t = threadIdx.x;
    const int col = t & 127, kh = t >> 7;
    float w[32];
#pragma unroll
    for (int k = 0; k < 32; k++) w[k] = wpre[(kh * 32 + k) * HH + col];
    const float bc = bpre[col];
    const int r0 = blockIdx.x * K1_ROWS;
    const int r1 = min(NN, r0 + K1_ROWS);
    float ls = 0.f, lq = 0.f;
    for (int rt = r0; rt < r1; rt += 8) {
        const int nr = min(8, r1 - rt);
        __syncthreads();
        for (int idx = t; idx < nr * FF; idx += 256) xs[idx] = x[rt * FF + idx];
        __syncthreads();
        float p[8];
#pragma unroll
        for (int i = 0; i < 8; i++) {
            p[i] = 0.f;
            if (i < nr) {
                float a0 = 0.f, a1 = 0.f, a2 = 0.f, a3 = 0.f;
                const float4* xv4 = (const float4*)&xs[i * FF + kh * 32];
#pragma unroll
                for (int k4 = 0; k4 < 8; k4++) {
                    float4 xv = xv4[k4];
                    a0 = fmaf(xv.x, w[4 * k4 + 0], a0);
                    a1 = fmaf(xv.y, w[4 * k4 + 1], a1);
                    a2 = fmaf(xv.z, w[4 * k4 + 2], a2);
                    a3 = fmaf(xv.w, w[4 * k4 + 3], a3);
                }
                p[i] = (a0 + a1) + (a2 + a3);
            }
        }
        if (kh) {
#pragma unroll
            for (int i = 0; i < 8; i++)
                if (i < nr) part[i * 128 + col] = p[i];
        }
        __syncthreads();
        if (!kh) {
#pragma unroll
            for (int i = 0; i < 8; i++)
                if (i < nr) {
                    float acc = p[i] + part[i * 128 + col] + bc;
                    g_y[(rt + i) * HH + col] = acc;
                    ls += acc;
                    lq = fmaf(acc, acc, lq);
                }
        }
    }
    if (!kh) {
        atomicAdd(&g_sum1[col], ls);
        atomicAdd(&g_sumsq1[col], lq);
    }
}

// ---------------- K2: 3xBF16 split dual GEMM, 512 threads / 16 warps ---------
#define HS_STRIDE 272
#define WS_STRIDE 528
#define HS_BYTES (128 * HS_STRIDE)   // 34816
#define WS_BYTES (128 * WS_STRIDE)   // 67584
#define K2M_SMEM (2 * HS_BYTES + 2 * WS_BYTES)   // 204800

__global__ void __launch_bounds__(512) k2m(const float* __restrict__ wcn,
                                           const float* __restrict__ bcn,
                                           const float* __restrict__ gpre,
                                           const float* __restrict__ bepre) {
    extern __shared__ __align__(16) char smem[];
    char* hs_hi = smem;
    char* hs_lo = smem + HS_BYTES;
    char* ws_hi = smem + 2 * HS_BYTES;
    char* ws_lo = smem + 2 * HS_BYTES + WS_BYTES;
    __shared__ float hscale[HH], hbias[HH], bcn_s[HH];
    const int t = threadIdx.x;
    const int lane = t & 31, wid = t >> 5;

    if (t < HH) {
        float mu  = g_sum1[t] * (1.f / NN);
        float var = g_sumsq1[t] * (1.f / NN) - mu * mu;
        float sc  = gpre[t] * rsqrtf(var + BN_EPSF);
        hscale[t] = sc;
        hbias[t]  = bepre[t] - mu * sc;
        bcn_s[t]  = bcn[t];
    }
    for (int idx = t; idx < HH * 256; idx += 512) {
        int k = idx >> 8, n = idx & 255;
        float w2 = wcn[(k + HH) * HH + (n & 127)];
        float v = (n < HH) ? (wcn[k * HH + n] - w2) : w2;
        __nv_bfloat16 hi = __float2bfloat16(v);
        float lo = v - __bfloat162float(hi);
        *(__nv_bfloat16*)(ws_hi + k * WS_STRIDE + n * 2) = hi;
        *(__nv_bfloat16*)(ws_lo + k * WS_STRIDE + n * 2) = __float2bfloat16(lo);
    }
    __syncthreads();

    const uint32_t wshi_base = smem_u32(ws_hi);
    const uint32_t wslo_base = smem_u32(ws_lo);
    const int n0w = wid * 16;
    uint32_t bhi[8][2][2], blo[8][2][2];
#pragma unroll
    for (int ks = 0; ks < 8; ks++)
#pragma unroll
        for (int nt = 0; nt < 2; nt++) {
            uint32_t roff = (ks * 16 + (lane & 15)) * WS_STRIDE + (n0w + nt * 8) * 2;
            LDSM_X2T(bhi[ks][nt][0], bhi[ks][nt][1], wshi_base + roff);
            LDSM_X2T(blo[ks][nt][0], blo[ks][nt][1], wslo_base + roff);
        }

    const uint32_t hshi_base = smem_u32(hs_hi);
    const uint32_t hslo_base = smem_u32(hs_lo);
    const int g = lane >> 2, tig = lane & 3;

    for (int tile = blockIdx.x; tile < NTILES; tile += gridDim.x) {
        const int rbase = tile * 128;
        __syncthreads();
#pragma unroll
        for (int i = 0; i < 4; i++) {
            int idx = t + i * 512;
            int row = idx >> 4;
            int k0 = (idx & 15) * 8;
            uint4 pk_hi = make_uint4(0u, 0u, 0u, 0u);
            uint4 pk_lo = make_uint4(0u, 0u, 0u, 0u);
            if (rbase + row < NN) {
                const float* yp = &g_y[(rbase + row) * HH + k0];
                float4 y0 = *(const float4*)yp;
                float4 y1 = *(const float4*)(yp + 4);
                float v[8];
                v[0] = fmaxf(fmaf(y0.x, hscale[k0 + 0], hbias[k0 + 0]), 0.f);
                v[1] = fmaxf(fmaf(y0.y, hscale[k0 + 1], hbias[k0 + 1]), 0.f);
                v[2] = fmaxf(fmaf(y0.z, hscale[k0 + 2], hbias[k0 + 2]), 0.f);
                v[3] = fmaxf(fmaf(y0.w, hscale[k0 + 3], hbias[k0 + 3]), 0.f);
                v[4] = fmaxf(fmaf(y1.x, hscale[k0 + 4], hbias[k0 + 4]), 0.f);
                v[5] = fmaxf(fmaf(y1.y, hscale[k0 + 5], hbias[k0 + 5]), 0.f);
                v[6] = fmaxf(fmaf(y1.z, hscale[k0 + 6], hbias[k0 + 6]), 0.f);
                v[7] = fmaxf(fmaf(y1.w, hscale[k0 + 7], hbias[k0 + 7]), 0.f);
                unsigned* ph = (unsigned*)&pk_hi;
                unsigned* pl = (unsigned*)&pk_lo;
#pragma unroll
                for (int j = 0; j < 4; j++)
                    split_pack(v[2 * j], v[2 * j + 1], ph[j], pl[j]);
            }
            uint32_t soff = row * HS_STRIDE + k0 * 2;
            *(uint4*)(hs_hi + soff) = pk_hi;
            *(uint4*)(hs_lo + soff) = pk_lo;
        }
        __syncthreads();

#pragma unroll 1
        for (int mt = 0; mt < 8; mt++) {
            float d[2][4];
#pragma unroll
            for (int nt = 0; nt < 2; nt++)
#pragma unroll
                for (int r = 0; r < 4; r++) d[nt][r] = 0.f;
#pragma unroll
            for (int ks = 0; ks < 8; ks++) {
                uint32_t ahi0, ahi1, ahi2, ahi3, alo0, alo1, alo2, alo3;
                uint32_t roff = (mt * 16 + (lane & 15)) * HS_STRIDE
                              + ks * 32 + (lane & 16);
                LDSM_X4(ahi0, ahi1, ahi2, ahi3, hshi_base + roff);
                LDSM_X4(alo0, alo1, alo2, alo3, hslo_base + roff);
#pragma unroll
                for (int nt = 0; nt < 2; nt++) {
                    MMA16816(d[nt][0], d[nt][1], d[nt][2], d[nt][3],
                             ahi0, ahi1, ahi2, ahi3, bhi[ks][nt][0], bhi[ks][nt][1]);
                    MMA16816(d[nt][0], d[nt][1], d[nt][2], d[nt][3],
                             alo0, alo1, alo2, alo3, bhi[ks][nt][0], bhi[ks][nt][1]);
                    MMA16816(d[nt][0], d[nt][1], d[nt][2], d[nt][3],
                             ahi0, ahi1, ahi2, ahi3, blo[ks][nt][0], blo[ks][nt][1]);
                }
            }
            const int r0 = rbase + mt * 16 + g;
            const int r1 = r0 + 8;
#pragma unroll
            for (int nt = 0; nt < 2; nt++) {
                int c = n0w + nt * 8 + tig * 2;
                if (c < HH) {
                    float2 v0 = make_float2(d[nt][0] + bcn_s[c], d[nt][1] + bcn_s[c + 1]);
                    float2 v1 = make_float2(d[nt][2] + bcn_s[c], d[nt][3] + bcn_s[c + 1]);
                    if (r0 < NN) *(float2*)&g_a[r0 * HH + c] = v0;
                    if (r1 < NN) *(float2*)&g_a[r1 * HH + c] = v1;
                } else {
                    unsigned p0, p1;
                    asm("cvt.rn.bf16x2.f32 %0, %1, %2;"
                        : "=r"(p0) : "f"(d[nt][1]), "f"(d[nt][0]));
                    asm("cvt.rn.bf16x2.f32 %0, %1, %2;"
                        : "=r"(p1) : "f"(d[nt][3]), "f"(d[nt][2]));
                    int cb = (c - HH) >> 1;
                    if (r0 < NN) g_bh[r0 * 64 + cb] = p0;
                    if (r1 < NN) g_bh[r1 * 64 + cb] = p1;
                }
            }
        }
    }
}

// ---------------- K3: TWO warps per node (edges split) -> pool ---------------
__device__ __forceinline__ void red_add_v4(float* p, float4 v) {
    asm volatile("red.global.add.v4.f32 [%0], {%1, %2, %3, %4};"
                 :: "l"(p), "f"(v.x), "f"(v.y), "f"(v.z), "f"(v.w) : "memory");
}

__device__ __forceinline__ void acc_edge(float4& acc, const float4& a, uint2 rb) {
    float b0 = __int_as_float(rb.x << 16);
    float b1 = __int_as_float(rb.x & 0xffff0000u);
    float b2 = __int_as_float(rb.y << 16);
    float b3 = __int_as_float(rb.y & 0xffff0000u);
    acc.x += fmaxf(a.x + b0, 0.f);
    acc.y += fmaxf(a.y + b1, 0.f);
    acc.z += fmaxf(a.z + b2, 0.f);
    acc.w += fmaxf(a.w + b3, 0.f);
}

__global__ void __launch_bounds__(256) k3(const int* __restrict__ seg) {
    const int gw = (blockIdx.x * 256 + threadIdx.x) >> 5;
    const int i = gw >> 1;
    if (i >= NN) return;
    const int half = gw & 1;
    const int lane = threadIdx.x & 31;
    const int deg = min(g_cnt[i], PAD);
    const int e0 = half ? (deg >> 1) : 0;
    const int e1 = half ? deg : (deg >> 1);
    if (e0 >= e1) return;
    const float4 a = *(const float4*)&g_a[i * HH + lane * 4];
    const int g = __ldg(seg + i);
    const int* al = g_adj + i * PAD;
    float4 acc = make_float4(0.f, 0.f, 0.f, 0.f);
    int j = e0;
    for (; j + 8 <= e1; j += 8) {
        int d[8];
#pragma unroll
        for (int u = 0; u < 8; u++) d[u] = __ldg(al + j + u);
        uint2 rb[8];
#pragma unroll
        for (int u = 0; u < 8; u++)
            rb[u] = *(const uint2*)&g_bh[d[u] * 64 + lane * 2];
#pragma unroll
        for (int u = 0; u < 8; u++) acc_edge(acc, a, rb[u]);
    }
    for (; j < e1; j++) {
        int d = __ldg(al + j);
        uint2 rb = *(const uint2*)&g_bh[d * 64 + lane * 2];
        acc_edge(acc, a, rb);
    }
    red_add_v4(&g_p[g * HH + lane * 4], acc);
}

// ---------------- K4: y2 = p @ w_post + b_post ; double col sums -------------
__global__ void __launch_bounds__(128) k4(const float* __restrict__ wpost,
                                          const float* __restrict__ bpost) {
    extern __shared__ float ws4[];
    __shared__ float ps[HH];
    const int t = threadIdx.x;
    for (int i = t; i < HH * HH; i += 128) ws4[i] = wpost[i];
    const float bc = bpost[t];
    const int r0 = blockIdx.x * (GG / 64);
    double bsum = 0.0, bsq = 0.0;
    __syncthreads();
    for (int r = r0; r < r0 + GG / 64; r++) {
        __syncthreads();
        ps[t] = g_p[r * HH + t];
        __syncthreads();
        float acc = bc;
#pragma unroll 8
        for (int k = 0; k < HH; k++) acc = fmaf(ps[k], ws4[k * HH + t], acc);
        g_y2[r * HH + t] = acc;
        bsum += (double)acc;
        bsq = fma((double)acc, (double)acc, bsq);
    }
    atomicAdd(&g_sum2[t], bsum);
    atomicAdd(&g_sumsq2[t], bsq);
}

// ---------------- K5: relu(BN(y2)) @ w_out + b_out -> sigmoid ----------------
__global__ void __launch_bounds__(256) k5(const float* __restrict__ gpost,
                                          const float* __restrict__ bepost,
                                          const float* __restrict__ wout,
                                          const float* __restrict__ bout,
                                          float* __restrict__ out) {
    const int r = (blockIdx.x * 256 + threadIdx.x) >> 5;
    const int lane = threadIdx.x & 31;
    if (r >= GG) return;
    float acc = 0.f;
#pragma unroll
    for (int j = 0; j < 4; j++) {
        int c = lane + 32 * j;
        double mu = g_sum2[c] * (1.0 / GG);
        float var = (float)(g_sumsq2[c] * (1.0 / GG) - mu * mu);
        float sc = gpost[c] * rsqrtf(var + BN_EPSF);
        float hb = bepost[c] - (float)mu * sc;
        float hn = fmaxf(fmaf(g_y2[r * HH + c], sc, hb), 0.f);
        acc += hn * wout[c];
    }
#pragma unroll
    for (int o = 16; o; o >>= 1) acc += __shfl_down_sync(0xffffffffu, acc, o);
    if (lane == 0) out[r] = 1.f / (1.f + expf(-(acc + bout[0])));
}

// ---------------- launch -----------------------------------------------------
extern "C" void kernel_launch(void* const* d_in, const int* in_sizes, int n_in,
                              void* d_out, int out_size) {
    const float* x      = (const float*)d_in[0];
    const int*   src    = (const int*)d_in[1];
    const int*   dst    = (const int*)d_in[2];
    const int*   seg    = (const int*)d_in[3];
    const float* w_pre  = (const float*)d_in[4];
    const float* b_pre  = (const float*)d_in[5];
    const float* gm_pre = (const float*)d_in[6];
    const float* be_pre = (const float*)d_in[7];
    const float* w_cn   = (const float*)d_in[8];
    const float* b_cn   = (const float*)d_in[9];
    const float* w_post = (const float*)d_in[10];
    const float* b_post = (const float*)d_in[11];
    const float* gm_post= (const float*)d_in[12];
    const float* be_post= (const float*)d_in[13];
    const float* w_out  = (const float*)d_in[14];
    const float* b_out  = (const float*)d_in[15];
    float* out = (float*)d_out;
    const int E = in_sizes[1];

    static cudaStream_t s2 = nullptr;
    static cudaEvent_t ev_fork = nullptr, ev_join = nullptr;
    if (!s2) {
        cudaStreamCreateWithFlags(&s2, cudaStreamNonBlocking);
        cudaEventCreateWithFlags(&ev_fork, cudaEventDisableTiming);
        cudaEventCreateWithFlags(&ev_join, cudaEventDisableTiming);
    }

    const int k4_smem = HH * HH * 4;
    cudaFuncSetAttribute(k2m, cudaFuncAttributeMaxDynamicSharedMemorySize, K2M_SMEM);
    cudaFuncSetAttribute(k4, cudaFuncAttributeMaxDynamicSharedMemorySize, k4_smem);

    kzero_p<<<(GG * HH + 255) / 256, 256>>>();                  // #1
    kzero_cnt<<<(NN + 255) / 256, 256>>>();                     // #2
    // fork: adjacency build on s2, concurrent with k1+k2m on main stream
    cudaEventRecord(ev_fork, 0);
    cudaStreamWaitEvent(s2, ev_fork, 0);
    kscat2<<<(E / 8 + 255) / 256, 256, 0, s2>>>(src, dst, E);   // #3
    cudaEventRecord(ev_join, s2);
    // main stream: node GEMMs
    k1<<<(NN + K1_ROWS - 1) / K1_ROWS, 256>>>(x, w_pre, b_pre); // #4 (profiled)
    k2m<<<148, 512, K2M_SMEM>>>(w_cn, b_cn, gm_pre, be_pre);    // #5
    // join: k3 needs adjacency + A/B
    cudaStreamWaitEvent(0, ev_join, 0);
    k3<<<(NN * 2 * 32 + 255) / 256, 256>>>(seg);                // #6
    k4<<<64, 128, k4_smem>>>(w_post, b_post);                   // #7
    k5<<<(GG * 32) / 256, 256>>>(gm_post, be_post, w_out, b_out, out);
}

// round 15
// speedup vs baseline: 1.0948x; 1.0948x over previous
#include <cuda_runtime.h>
#include <cuda_bf16.h>
#include <cstdint>

#define NN 50000
#define FF 64
#define HH 128
#define GG 512
#define BN_EPSF 1e-3f
#define NTILES ((NN + 127) / 128)   // 391
#define PAD 96                       // max supported degree per node

// ---------------- scratch (device globals; no dynamic alloc allowed) ----------
static __device__ float    g_y[NN * HH];   // pre-GEMM output (pre-BN)
static __device__ float    g_a[NN * HH];   // A = h @ (W1-W2) + b_cn  (fp32)
static __device__ unsigned g_bh[NN * 64];  // B = h @ W2 as bf16x2 pairs
static __device__ float    g_p[GG * HH];   // pooled per-graph sums
static __device__ float    g_y2[GG * HH];  // post-GEMM output (pre-BN)
static __device__ float    g_sum1[HH];
static __device__ float    g_sumsq1[HH];
static __device__ double   g_sum2[HH];
static __device__ double   g_sumsq2[HH];
// padded adjacency
static __device__ int      g_cnt[NN];          // degree (atomic cursor)
static __device__ int      g_adj[NN * PAD];    // dst per edge, grouped by src

// ---------------- PTX helpers (sm_80-era: ldmatrix + mma.sync) ---------------
__device__ __forceinline__ uint32_t smem_u32(const void* p) {
    uint32_t a;
    asm("{ .reg .u64 t; cvta.to.shared.u64 t, %1; cvt.u32.u64 %0, t; }"
        : "=r"(a) : "l"(p));
    return a;
}

#define LDSM_X4(r0, r1, r2, r3, addr)                                          \
    asm volatile("ldmatrix.sync.aligned.m8n8.x4.shared.b16 {%0,%1,%2,%3}, [%4];" \
                 : "=r"(r0), "=r"(r1), "=r"(r2), "=r"(r3) : "r"(addr))

#define LDSM_X2T(r0, r1, addr)                                                 \
    asm volatile("ldmatrix.sync.aligned.m8n8.x2.trans.shared.b16 {%0,%1}, [%2];" \
                 : "=r"(r0), "=r"(r1) : "r"(addr))

#define MMA16816(d0, d1, d2, d3, a0, a1, a2, a3, b0, b1)                       \
    asm volatile("mma.sync.aligned.m16n8k16.row.col.f32.bf16.bf16.f32 "        \
                 "{%0,%1,%2,%3}, {%4,%5,%6,%7}, {%8,%9}, {%0,%1,%2,%3};"       \
                 : "+f"(d0), "+f"(d1), "+f"(d2), "+f"(d3)                      \
                 : "r"(a0), "r"(a1), "r"(a2), "r"(a3), "r"(b0), "r"(b1))

__device__ __forceinline__ void split_pack(float a0, float a1,
                                           unsigned& hp, unsigned& lp) {
    asm("cvt.rn.bf16x2.f32 %0, %1, %2;" : "=r"(hp) : "f"(a1), "f"(a0));
    float h0 = __uint_as_float(hp << 16);
    float h1 = __uint_as_float(hp & 0xffff0000u);
    float l0 = a0 - h0, l1 = a1 - h1;
    asm("cvt.rn.bf16x2.f32 %0, %1, %2;" : "=r"(lp) : "f"(l1), "f"(l0));
}

// ---------------- zero: pooled sums + BN accumulators + adjacency counters ---
__global__ void kzero() {
    int t = blockIdx.x * blockDim.x + threadIdx.x;
    if (t < GG * HH) g_p[t] = 0.f;
    if (t < NN) g_cnt[t] = 0;
    if (t < HH) {
        g_sum1[t] = 0.f; g_sumsq1[t] = 0.f;
        g_sum2[t] = 0.0; g_sumsq2[t] = 0.0;
    }
}

// ---------------- adjacency build: single pass, padded slots -----------------
__global__ void kscat2(const int* __restrict__ src, const int* __restrict__ dst,
                       int E) {
    int base = (blockIdx.x * blockDim.x + threadIdx.x) * 8;
#pragma unroll
    for (int u = 0; u < 8; u++) {
        int e = base + u;
        if (e < E) {
            int s = __ldg(src + e);
            int pos = atomicAdd(&g_cnt[s], 1);
            if (pos < PAD) g_adj[s * PAD + pos] = __ldg(dst + e);
        }
    }
}

// ---------------- K1: y = x @ w_pre + b_pre ; per-column sum/sumsq -----------
// R12 version: 128 threads, 4 rotating accumulators (measured 39.7us).
#define K1_ROWS 44
__global__ void __launch_bounds__(128) k1(const float* __restrict__ x,
                                          const float* __restrict__ wpre,
                                          const float* __restrict__ bpre) {
    __shared__ __align__(16) float xs[8 * FF];
    const int t = threadIdx.x;
    float w[FF];
#pragma unroll
    for (int k = 0; k < FF; k++) w[k] = wpre[k * HH + t];
    const float bc = bpre[t];
    const int r0 = blockIdx.x * K1_ROWS;
    const int r1 = min(NN, r0 + K1_ROWS);
    float ls = 0.f, lq = 0.f;
    for (int rt = r0; rt < r1; rt += 8) {
        const int nr = min(8, r1 - rt);
        __syncthreads();
        for (int idx = t; idx < nr * FF; idx += 128) xs[idx] = x[rt * FF + idx];
        __syncthreads();
#pragma unroll 1
        for (int i = 0; i < nr; i++) {
            float a0 = 0.f, a1 = 0.f, a2 = 0.f, a3 = 0.f;
            const float4* xv4 = (const float4*)&xs[i * FF];
#pragma unroll
            for (int k4 = 0; k4 < FF / 4; k4++) {
                float4 xv = xv4[k4];
                a0 = fmaf(xv.x, w[4 * k4 + 0], a0);
                a1 = fmaf(xv.y, w[4 * k4 + 1], a1);
                a2 = fmaf(xv.z, w[4 * k4 + 2], a2);
                a3 = fmaf(xv.w, w[4 * k4 + 3], a3);
            }
            float acc = ((a0 + a1) + (a2 + a3)) + bc;
            g_y[(rt + i) * HH + t] = acc;
            ls += acc;
            lq = fmaf(acc, acc, lq);
        }
    }
    atomicAdd(&g_sum1[t], ls);
    atomicAdd(&g_sumsq1[t], lq);
}

// ---------------- K2: 3xBF16 split dual GEMM, 512 threads / 16 warps ---------
// Dual accumulators per nt: dh <- hi*hi (8-chain), dl <- lo*hi + hi*lo (16-chain)
#define HS_STRIDE 272
#define WS_STRIDE 528
#define HS_BYTES (128 * HS_STRIDE)   // 34816
#define WS_BYTES (128 * WS_STRIDE)   // 67584
#define K2M_SMEM (2 * HS_BYTES + 2 * WS_BYTES)   // 204800

__global__ void __launch_bounds__(512) k2m(const float* __restrict__ wcn,
                                           const float* __restrict__ bcn,
                                           const float* __restrict__ gpre,
                                           const float* __restrict__ bepre) {
    extern __shared__ __align__(16) char smem[];
    char* hs_hi = smem;
    char* hs_lo = smem + HS_BYTES;
    char* ws_hi = smem + 2 * HS_BYTES;
    char* ws_lo = smem + 2 * HS_BYTES + WS_BYTES;
    __shared__ float hscale[HH], hbias[HH], bcn_s[HH];
    const int t = threadIdx.x;
    const int lane = t & 31, wid = t >> 5;

    if (t < HH) {
        float mu  = g_sum1[t] * (1.f / NN);
        float var = g_sumsq1[t] * (1.f / NN) - mu * mu;
        float sc  = gpre[t] * rsqrtf(var + BN_EPSF);
        hscale[t] = sc;
        hbias[t]  = bepre[t] - mu * sc;
        bcn_s[t]  = bcn[t];
    }
    for (int idx = t; idx < HH * 256; idx += 512) {
        int k = idx >> 8, n = idx & 255;
        float w2 = wcn[(k + HH) * HH + (n & 127)];
        float v = (n < HH) ? (wcn[k * HH + n] - w2) : w2;
        __nv_bfloat16 hi = __float2bfloat16(v);
        float lo = v - __bfloat162float(hi);
        *(__nv_bfloat16*)(ws_hi + k * WS_STRIDE + n * 2) = hi;
        *(__nv_bfloat16*)(ws_lo + k * WS_STRIDE + n * 2) = __float2bfloat16(lo);
    }
    __syncthreads();

    const uint32_t wshi_base = smem_u32(ws_hi);
    const uint32_t wslo_base = smem_u32(ws_lo);
    const int n0w = wid * 16;
    uint32_t bhi[8][2][2], blo[8][2][2];
#pragma unroll
    for (int ks = 0; ks < 8; ks++)
#pragma unroll
        for (int nt = 0; nt < 2; nt++) {
            uint32_t roff = (ks * 16 + (lane & 15)) * WS_STRIDE + (n0w + nt * 8) * 2;
            LDSM_X2T(bhi[ks][nt][0], bhi[ks][nt][1], wshi_base + roff);
            LDSM_X2T(blo[ks][nt][0], blo[ks][nt][1], wslo_base + roff);
        }

    const uint32_t hshi_base = smem_u32(hs_hi);
    const uint32_t hslo_base = smem_u32(hs_lo);
    const int g = lane >> 2, tig = lane & 3;

    for (int tile = blockIdx.x; tile < NTILES; tile += gridDim.x) {
        const int rbase = tile * 128;
        __syncthreads();
#pragma unroll
        for (int i = 0; i < 4; i++) {
            int idx = t + i * 512;
            int row = idx >> 4;
            int k0 = (idx & 15) * 8;
            uint4 pk_hi = make_uint4(0u, 0u, 0u, 0u);
            uint4 pk_lo = make_uint4(0u, 0u, 0u, 0u);
            if (rbase + row < NN) {
                const float* yp = &g_y[(rbase + row) * HH + k0];
                float4 y0 = *(const float4*)yp;
                float4 y1 = *(const float4*)(yp + 4);
                float v[8];
                v[0] = fmaxf(fmaf(y0.x, hscale[k0 + 0], hbias[k0 + 0]), 0.f);
                v[1] = fmaxf(fmaf(y0.y, hscale[k0 + 1], hbias[k0 + 1]), 0.f);
                v[2] = fmaxf(fmaf(y0.z, hscale[k0 + 2], hbias[k0 + 2]), 0.f);
                v[3] = fmaxf(fmaf(y0.w, hscale[k0 + 3], hbias[k0 + 3]), 0.f);
                v[4] = fmaxf(fmaf(y1.x, hscale[k0 + 4], hbias[k0 + 4]), 0.f);
                v[5] = fmaxf(fmaf(y1.y, hscale[k0 + 5], hbias[k0 + 5]), 0.f);
                v[6] = fmaxf(fmaf(y1.z, hscale[k0 + 6], hbias[k0 + 6]), 0.f);
                v[7] = fmaxf(fmaf(y1.w, hscale[k0 + 7], hbias[k0 + 7]), 0.f);
                unsigned* ph = (unsigned*)&pk_hi;
                unsigned* pl = (unsigned*)&pk_lo;
#pragma unroll
                for (int j = 0; j < 4; j++)
                    split_pack(v[2 * j], v[2 * j + 1], ph[j], pl[j]);
            }
            uint32_t soff = row * HS_STRIDE + k0 * 2;
            *(uint4*)(hs_hi + soff) = pk_hi;
            *(uint4*)(hs_lo + soff) = pk_lo;
        }
        __syncthreads();

#pragma unroll 1
        for (int mt = 0; mt < 8; mt++) {
            float dh[2][4], dl[2][4];
#pragma unroll
            for (int nt = 0; nt < 2; nt++)
#pragma unroll
                for (int r = 0; r < 4; r++) { dh[nt][r] = 0.f; dl[nt][r] = 0.f; }
#pragma unroll
            for (int ks = 0; ks < 8; ks++) {
                uint32_t ahi0, ahi1, ahi2, ahi3, alo0, alo1, alo2, alo3;
                uint32_t roff = (mt * 16 + (lane & 15)) * HS_STRIDE
                              + ks * 32 + (lane & 16);
                LDSM_X4(ahi0, ahi1, ahi2, ahi3, hshi_base + roff);
                LDSM_X4(alo0, alo1, alo2, alo3, hslo_base + roff);
#pragma unroll
                for (int nt = 0; nt < 2; nt++) {
                    MMA16816(dh[nt][0], dh[nt][1], dh[nt][2], dh[nt][3],
                             ahi0, ahi1, ahi2, ahi3, bhi[ks][nt][0], bhi[ks][nt][1]);
                    MMA16816(dl[nt][0], dl[nt][1], dl[nt][2], dl[nt][3],
                             alo0, alo1, alo2, alo3, bhi[ks][nt][0], bhi[ks][nt][1]);
                    MMA16816(dl[nt][0], dl[nt][1], dl[nt][2], dl[nt][3],
                             ahi0, ahi1, ahi2, ahi3, blo[ks][nt][0], blo[ks][nt][1]);
                }
            }
            const int r0 = rbase + mt * 16 + g;
            const int r1 = r0 + 8;
#pragma unroll
            for (int nt = 0; nt < 2; nt++) {
                int c = n0w + nt * 8 + tig * 2;
                float s0 = dh[nt][0] + dl[nt][0];
                float s1 = dh[nt][1] + dl[nt][1];
                float s2 = dh[nt][2] + dl[nt][2];
                float s3 = dh[nt][3] + dl[nt][3];
                if (c < HH) {
                    float2 v0 = make_float2(s0 + bcn_s[c], s1 + bcn_s[c + 1]);
                    float2 v1 = make_float2(s2 + bcn_s[c], s3 + bcn_s[c + 1]);
                    if (r0 < NN) *(float2*)&g_a[r0 * HH + c] = v0;
                    if (r1 < NN) *(float2*)&g_a[r1 * HH + c] = v1;
                } else {
                    unsigned p0, p1;
                    asm("cvt.rn.bf16x2.f32 %0, %1, %2;" : "=r"(p0) : "f"(s1), "f"(s0));
                    asm("cvt.rn.bf16x2.f32 %0, %1, %2;" : "=r"(p1) : "f"(s3), "f"(s2));
                    int cb = (c - HH) >> 1;
                    if (r0 < NN) g_bh[r0 * 64 + cb] = p0;
                    if (r1 < NN) g_bh[r1 * 64 + cb] = p1;
                }
            }
        }
    }
}

// ---------------- K3: TWO warps per node (edges split) -> pool ---------------
__device__ __forceinline__ void red_add_v4(float* p, float4 v) {
    asm volatile("red.global.add.v4.f32 [%0], {%1, %2, %3, %4};"
                 :: "l"(p), "f"(v.x), "f"(v.y), "f"(v.z), "f"(v.w) : "memory");
}

__device__ __forceinline__ void acc_edge(float4& acc, const float4& a, uint2 rb) {
    float b0 = __int_as_float(rb.x << 16);
    float b1 = __int_as_float(rb.x & 0xffff0000u);
    float b2 = __int_as_float(rb.y << 16);
    float b3 = __int_as_float(rb.y & 0xffff0000u);
    acc.x += fmaxf(a.x + b0, 0.f);
    acc.y += fmaxf(a.y + b1, 0.f);
    acc.z += fmaxf(a.z + b2, 0.f);
    acc.w += fmaxf(a.w + b3, 0.f);
}

__global__ void __launch_bounds__(256) k3(const int* __restrict__ seg) {
    const int gw = (blockIdx.x * 256 + threadIdx.x) >> 5;
    const int i = gw >> 1;
    if (i >= NN) return;
    const int half = gw & 1;
    const int lane = threadIdx.x & 31;
    const int deg = min(g_cnt[i], PAD);
    const int e0 = half ? (deg >> 1) : 0;
    const int e1 = half ? deg : (deg >> 1);
    if (e0 >= e1) return;
    const float4 a = *(const float4*)&g_a[i * HH + lane * 4];
    const int g = __ldg(seg + i);
    const int* al = g_adj + i * PAD;
    float4 acc = make_float4(0.f, 0.f, 0.f, 0.f);
    int j = e0;
    for (; j + 8 <= e1; j += 8) {
        int d[8];
#pragma unroll
        for (int u = 0; u < 8; u++) d[u] = __ldg(al + j + u);
        uint2 rb[8];
#pragma unroll
        for (int u = 0; u < 8; u++)
            rb[u] = *(const uint2*)&g_bh[d[u] * 64 + lane * 2];
#pragma unroll
        for (int u = 0; u < 8; u++) acc_edge(acc, a, rb[u]);
    }
    for (; j < e1; j++) {
        int d = __ldg(al + j);
        uint2 rb = *(const uint2*)&g_bh[d * 64 + lane * 2];
        acc_edge(acc, a, rb);
    }
    red_add_v4(&g_p[g * HH + lane * 4], acc);
}

// ---------------- K4: y2 = p @ w_post + b_post ; double col sums -------------
__global__ void __launch_bounds__(128) k4(const float* __restrict__ wpost,
                                          const float* __restrict__ bpost) {
    extern __shared__ float ws4[];
    __shared__ float ps[HH];
    const int t = threadIdx.x;
    for (int i = t; i < HH * HH; i += 128) ws4[i] = wpost[i];
    const float bc = bpost[t];
    const int r0 = blockIdx.x * (GG / 64);
    double bsum = 0.0, bsq = 0.0;
    __syncthreads();
    for (int r = r0; r < r0 + GG / 64; r++) {
        __syncthreads();
        ps[t] = g_p[r * HH + t];
        __syncthreads();
        float acc = bc;
#pragma unroll 8
        for (int k = 0; k < HH; k++) acc = fmaf(ps[k], ws4[k * HH + t], acc);
        g_y2[r * HH + t] = acc;
        bsum += (double)acc;
        bsq = fma((double)acc, (double)acc, bsq);
    }
    atomicAdd(&g_sum2[t], bsum);
    atomicAdd(&g_sumsq2[t], bsq);
}

// ---------------- K5: relu(BN(y2)) @ w_out + b_out -> sigmoid ----------------
__global__ void __launch_bounds__(256) k5(const float* __restrict__ gpost,
                                          const float* __restrict__ bepost,
                                          const float* __restrict__ wout,
                                          const float* __restrict__ bout,
                                          float* __restrict__ out) {
    const int r = (blockIdx.x * 256 + threadIdx.x) >> 5;
    const int lane = threadIdx.x & 31;
    if (r >= GG) return;
    float acc = 0.f;
#pragma unroll
    for (int j = 0; j < 4; j++) {
        int c = lane + 32 * j;
        double mu = g_sum2[c] * (1.0 / GG);
        float var = (float)(g_sumsq2[c] * (1.0 / GG) - mu * mu);
        float sc = gpost[c] * rsqrtf(var + BN_EPSF);
        float hb = bepost[c] - (float)mu * sc;
        float hn = fmaxf(fmaf(g_y2[r * HH + c], sc, hb), 0.f);
        acc += hn * wout[c];
    }
#pragma unroll
    for (int o = 16; o; o >>= 1) acc += __shfl_down_sync(0xffffffffu, acc, o);
    if (lane == 0) out[r] = 1.f / (1.f + expf(-(acc + bout[0])));
}

// ---------------- launch -----------------------------------------------------
extern "C" void kernel_launch(void* const* d_in, const int* in_sizes, int n_in,
                              void* d_out, int out_size) {
    const float* x      = (const float*)d_in[0];
    const int*   src    = (const int*)d_in[1];
    const int*   dst    = (const int*)d_in[2];
    const int*   seg    = (const int*)d_in[3];
    const float* w_pre  = (const float*)d_in[4];
    const float* b_pre  = (const float*)d_in[5];
    const float* gm_pre = (const float*)d_in[6];
    const float* be_pre = (const float*)d_in[7];
    const float* w_cn   = (const float*)d_in[8];
    const float* b_cn   = (const float*)d_in[9];
    const float* w_post = (const float*)d_in[10];
    const float* b_post = (const float*)d_in[11];
    const float* gm_post= (const float*)d_in[12];
    const float* be_post= (const float*)d_in[13];
    const float* w_out  = (const float*)d_in[14];
    const float* b_out  = (const float*)d_in[15];
    float* out = (float*)d_out;
    const int E = in_sizes[1];

    static cudaStream_t s2 = nullptr;
    static cudaEvent_t ev_fork = nullptr, ev_join = nullptr;
    if (!s2) {
        cudaStreamCreateWithFlags(&s2, cudaStreamNonBlocking);
        cudaEventCreateWithFlags(&ev_fork, cudaEventDisableTiming);
        cudaEventCreateWithFlags(&ev_join, cudaEventDisableTiming);
    }

    const int k4_smem = HH * HH * 4;
    cudaFuncSetAttribute(k2m, cudaFuncAttributeMaxDynamicSharedMemorySize, K2M_SMEM);
    cudaFuncSetAttribute(k4, cudaFuncAttributeMaxDynamicSharedMemorySize, k4_smem);

    // #1: zero everything
    kzero<<<(GG * HH + 255) / 256, 256>>>();
    // fork: adjacency build on s2, concurrent with k1+k2m on main stream
    cudaEventRecord(ev_fork, 0);
    cudaStreamWaitEvent(s2, ev_fork, 0);
    kscat2<<<(E / 8 + 255) / 256, 256, 0, s2>>>(src, dst, E);   // #2
    cudaEventRecord(ev_join, s2);
    // main stream: node GEMMs
    k1<<<(NN + K1_ROWS - 1) / K1_ROWS, 128>>>(x, w_pre, b_pre); // #3
    k2m<<<148, 512, K2M_SMEM>>>(w_cn, b_cn, gm_pre, be_pre);    // #4 (profiled)
    // join: k3 needs adjacency + A/B
    cudaStreamWaitEvent(0, ev_join, 0);
    k3<<<(NN * 2 * 32 + 255) / 256, 256>>>(seg);                // #5
    k4<<<64, 128, k4_smem>>>(w_post, b_post);                   // #6
    k5<<<(GG * 32) / 256, 256>>>(gm_post, be_post, w_out, b_out, out);
}

// round 16
// speedup vs baseline: 1.1038x; 1.0082x over previous
#include <cuda_runtime.h>
#include <cuda_bf16.h>
#include <cstdint>

#define NN 50000
#define FF 64
#define HH 128
#define GG 512
#define BN_EPSF 1e-3f
#define PAD 96                       // max supported degree per node
#define TILE 64
#define NT2 ((50048) / TILE)         // 782 tiles of 64 rows
#define NPAD (NT2 * TILE)            // 50048 padded rows for g_y

// ---------------- scratch (device globals; no dynamic alloc allowed) ----------
static __device__ float    g_y[NPAD * HH]; // pre-GEMM output (pre-BN), padded
static __device__ float    g_a[NN * HH];   // A = h @ (W1-W2) + b_cn  (fp32)
static __device__ unsigned g_bh[NN * 64];  // B = h @ W2 as bf16x2 pairs
static __device__ float    g_p[GG * HH];   // pooled per-graph sums
static __device__ float    g_y2[GG * HH];  // post-GEMM output (pre-BN)
static __device__ float    g_sum1[HH];
static __device__ float    g_sumsq1[HH];
static __device__ double   g_sum2[HH];
static __device__ double   g_sumsq2[HH];
// padded adjacency
static __device__ int      g_cnt[NN];          // degree (atomic cursor)
static __device__ int      g_adj[NN * PAD];    // dst per edge, grouped by src

// ---------------- PTX helpers ---------------
__device__ __forceinline__ uint32_t smem_u32(const void* p) {
    uint32_t a;
    asm("{ .reg .u64 t; cvta.to.shared.u64 t, %1; cvt.u32.u64 %0, t; }"
        : "=r"(a) : "l"(p));
    return a;
}

#define LDSM_X4(r0, r1, r2, r3, addr)                                          \
    asm volatile("ldmatrix.sync.aligned.m8n8.x4.shared.b16 {%0,%1,%2,%3}, [%4];" \
                 : "=r"(r0), "=r"(r1), "=r"(r2), "=r"(r3) : "r"(addr))

#define LDSM_X2T(r0, r1, addr)                                                 \
    asm volatile("ldmatrix.sync.aligned.m8n8.x2.trans.shared.b16 {%0,%1}, [%2];" \
                 : "=r"(r0), "=r"(r1) : "r"(addr))

#define MMA16816(d0, d1, d2, d3, a0, a1, a2, a3, b0, b1)                       \
    asm volatile("mma.sync.aligned.m16n8k16.row.col.f32.bf16.bf16.f32 "        \
                 "{%0,%1,%2,%3}, {%4,%5,%6,%7}, {%8,%9}, {%0,%1,%2,%3};"       \
                 : "+f"(d0), "+f"(d1), "+f"(d2), "+f"(d3)                      \
                 : "r"(a0), "r"(a1), "r"(a2), "r"(a3), "r"(b0), "r"(b1))

#define CP_ASYNC16(dst, src)                                                   \
    asm volatile("cp.async.ca.shared.global [%0], [%1], 16;"                   \
                 :: "r"(dst), "l"(src))
#define CP_COMMIT() asm volatile("cp.async.commit_group;" ::: "memory")
#define CP_WAIT0()  asm volatile("cp.async.wait_group 0;" ::: "memory")

__device__ __forceinline__ void split_pack(float a0, float a1,
                                           unsigned& hp, unsigned& lp) {
    asm("cvt.rn.bf16x2.f32 %0, %1, %2;" : "=r"(hp) : "f"(a1), "f"(a0));
    float h0 = __uint_as_float(hp << 16);
    float h1 = __uint_as_float(hp & 0xffff0000u);
    float l0 = a0 - h0, l1 = a1 - h1;
    asm("cvt.rn.bf16x2.f32 %0, %1, %2;" : "=r"(lp) : "f"(l1), "f"(l0));
}

// ---------------- zero: pooled sums + BN accumulators + adjacency counters ---
__global__ void kzero() {
    int t = blockIdx.x * blockDim.x + threadIdx.x;
    if (t < GG * HH) g_p[t] = 0.f;
    if (t < NN) g_cnt[t] = 0;
    if (t < HH) {
        g_sum1[t] = 0.f; g_sumsq1[t] = 0.f;
        g_sum2[t] = 0.0; g_sumsq2[t] = 0.0;
    }
}

// ---------------- adjacency build: single pass, padded slots -----------------
__global__ void kscat2(const int* __restrict__ src, const int* __restrict__ dst,
                       int E) {
    int base = (blockIdx.x * blockDim.x + threadIdx.x) * 8;
#pragma unroll
    for (int u = 0; u < 8; u++) {
        int e = base + u;
        if (e < E) {
            int s = __ldg(src + e);
            int pos = atomicAdd(&g_cnt[s], 1);
            if (pos < PAD) g_adj[s * PAD + pos] = __ldg(dst + e);
        }
    }
}

// ---------------- K1: y = x @ w_pre + b_pre ; per-column sum/sumsq -----------
#define K1_ROWS 44
__global__ void __launch_bounds__(128) k1(const float* __restrict__ x,
                                          const float* __restrict__ wpre,
                                          const float* __restrict__ bpre) {
    __shared__ __align__(16) float xs[8 * FF];
    const int t = threadIdx.x;
    float w[FF];
#pragma unroll
    for (int k = 0; k < FF; k++) w[k] = wpre[k * HH + t];
    const float bc = bpre[t];
    const int r0 = blockIdx.x * K1_ROWS;
    const int r1 = min(NN, r0 + K1_ROWS);
    float ls = 0.f, lq = 0.f;
    for (int rt = r0; rt < r1; rt += 8) {
        const int nr = min(8, r1 - rt);
        __syncthreads();
        for (int idx = t; idx < nr * FF; idx += 128) xs[idx] = x[rt * FF + idx];
        __syncthreads();
#pragma unroll 1
        for (int i = 0; i < nr; i++) {
            float a0 = 0.f, a1 = 0.f, a2 = 0.f, a3 = 0.f;
            const float4* xv4 = (const float4*)&xs[i * FF];
#pragma unroll
            for (int k4 = 0; k4 < FF / 4; k4++) {
                float4 xv = xv4[k4];
                a0 = fmaf(xv.x, w[4 * k4 + 0], a0);
                a1 = fmaf(xv.y, w[4 * k4 + 1], a1);
                a2 = fmaf(xv.z, w[4 * k4 + 2], a2);
                a3 = fmaf(xv.w, w[4 * k4 + 3], a3);
            }
            float acc = ((a0 + a1) + (a2 + a3)) + bc;
            g_y[(rt + i) * HH + t] = acc;
            ls += acc;
            lq = fmaf(acc, acc, lq);
        }
    }
    atomicAdd(&g_sum1[t], ls);
    atomicAdd(&g_sumsq1[t], lq);
}

// ---------------- K2: 3xBF16 split dual GEMM, cp.async pipelined -------------
// 64-row tiles; yraw smem buffer filled by cp.async overlapping MMA phase.
#define HS_STRIDE 272
#define WS_STRIDE 528
#define YR_STRIDE 136                 // floats per yraw row (544B)
#define HS_BYTES (TILE * HS_STRIDE)   // 17408
#define WS_BYTES (128 * WS_STRIDE)    // 67584
#define YR_BYTES (TILE * YR_STRIDE * 4) // 34816
#define K2M_SMEM (2 * HS_BYTES + 2 * WS_BYTES + YR_BYTES)  // 204800

__global__ void __launch_bounds__(512) k2m(const float* __restrict__ wcn,
                                           const float* __restrict__ bcn,
                                           const float* __restrict__ gpre,
                                           const float* __restrict__ bepre) {
    extern __shared__ __align__(16) char smem[];
    char*  hs_hi = smem;
    char*  hs_lo = smem + HS_BYTES;
    char*  ws_hi = smem + 2 * HS_BYTES;
    char*  ws_lo = smem + 2 * HS_BYTES + WS_BYTES;
    float* yraw  = (float*)(smem + 2 * HS_BYTES + 2 * WS_BYTES);
    __shared__ float hscale[HH], hbias[HH], bcn_s[HH];
    const int t = threadIdx.x;
    const int lane = t & 31, wid = t >> 5;

    if (t < HH) {
        float mu  = g_sum1[t] * (1.f / NN);
        float var = g_sumsq1[t] * (1.f / NN) - mu * mu;
        float sc  = gpre[t] * rsqrtf(var + BN_EPSF);
        hscale[t] = sc;
        hbias[t]  = bepre[t] - mu * sc;
        bcn_s[t]  = bcn[t];
    }
    for (int idx = t; idx < HH * 256; idx += 512) {
        int k = idx >> 8, n = idx & 255;
        float w2 = wcn[(k + HH) * HH + (n & 127)];
        float v = (n < HH) ? (wcn[k * HH + n] - w2) : w2;
        __nv_bfloat16 hi = __float2bfloat16(v);
        float lo = v - __bfloat162float(hi);
        *(__nv_bfloat16*)(ws_hi + k * WS_STRIDE + n * 2) = hi;
        *(__nv_bfloat16*)(ws_lo + k * WS_STRIDE + n * 2) = __float2bfloat16(lo);
    }
    __syncthreads();

    const uint32_t wshi_base = smem_u32(ws_hi);
    const uint32_t wslo_base = smem_u32(ws_lo);
    const int n0w = wid * 16;
    uint32_t bhi[8][2][2], blo[8][2][2];
#pragma unroll
    for (int ks = 0; ks < 8; ks++)
#pragma unroll
        for (int nt = 0; nt < 2; nt++) {
            uint32_t roff = (ks * 16 + (lane & 15)) * WS_STRIDE + (n0w + nt * 8) * 2;
            LDSM_X2T(bhi[ks][nt][0], bhi[ks][nt][1], wshi_base + roff);
            LDSM_X2T(blo[ks][nt][0], blo[ks][nt][1], wslo_base + roff);
        }

    const uint32_t hshi_base = smem_u32(hs_hi);
    const uint32_t hslo_base = smem_u32(hs_lo);
    const uint32_t yr_base   = smem_u32(yraw);
    const int g = lane >> 2, tig = lane & 3;

    // prologue: load first tile's y into yraw
    int tile = blockIdx.x;
    if (tile < NT2) {
#pragma unroll
        for (int i = 0; i < 4; i++) {
            int idx = t + i * 512;           // 0..2047
            int row = idx >> 5, kg = idx & 31;
            CP_ASYNC16(yr_base + (row * YR_STRIDE + kg * 4) * 4,
                       &g_y[(tile * TILE + row) * HH + kg * 4]);
        }
    }
    CP_COMMIT();
    CP_WAIT0();
    __syncthreads();

    for (; tile < NT2; tile += 148) {
        const int rbase = tile * TILE;
        // convert yraw -> hs (hi/lo split), smem-to-smem
#pragma unroll
        for (int i = 0; i < 2; i++) {
            int idx = t + i * 512;           // 0..1023
            int row = idx >> 4;
            int k0 = (idx & 15) * 8;
            const float* yp = &yraw[row * YR_STRIDE + k0];
            float4 y0 = *(const float4*)yp;
            float4 y1 = *(const float4*)(yp + 4);
            float v[8];
            v[0] = fmaxf(fmaf(y0.x, hscale[k0 + 0], hbias[k0 + 0]), 0.f);
            v[1] = fmaxf(fmaf(y0.y, hscale[k0 + 1], hbias[k0 + 1]), 0.f);
            v[2] = fmaxf(fmaf(y0.z, hscale[k0 + 2], hbias[k0 + 2]), 0.f);
            v[3] = fmaxf(fmaf(y0.w, hscale[k0 + 3], hbias[k0 + 3]), 0.f);
            v[4] = fmaxf(fmaf(y1.x, hscale[k0 + 4], hbias[k0 + 4]), 0.f);
            v[5] = fmaxf(fmaf(y1.y, hscale[k0 + 5], hbias[k0 + 5]), 0.f);
            v[6] = fmaxf(fmaf(y1.z, hscale[k0 + 6], hbias[k0 + 6]), 0.f);
            v[7] = fmaxf(fmaf(y1.w, hscale[k0 + 7], hbias[k0 + 7]), 0.f);
            uint4 pk_hi, pk_lo;
            unsigned* ph = (unsigned*)&pk_hi;
            unsigned* pl = (unsigned*)&pk_lo;
#pragma unroll
            for (int j = 0; j < 4; j++)
                split_pack(v[2 * j], v[2 * j + 1], ph[j], pl[j]);
            uint32_t soff = row * HS_STRIDE + k0 * 2;
            *(uint4*)(hs_hi + soff) = pk_hi;
            *(uint4*)(hs_lo + soff) = pk_lo;
        }
        __syncthreads();   // hs ready; yraw free for next tile

        // issue next tile's cp.async (overlaps MMA below)
        int nxt = tile + 148;
        if (nxt < NT2) {
#pragma unroll
            for (int i = 0; i < 4; i++) {
                int idx = t + i * 512;
                int row = idx >> 5, kg = idx & 31;
                CP_ASYNC16(yr_base + (row * YR_STRIDE + kg * 4) * 4,
                           &g_y[(nxt * TILE + row) * HH + kg * 4]);
            }
        }
        CP_COMMIT();

        // MMA: 4 m16-tiles x 8 k16-steps x 2 n8-tiles x 3 terms
#pragma unroll 1
        for (int mt = 0; mt < 4; mt++) {
            float dh[2][4], dl[2][4];
#pragma unroll
            for (int nt = 0; nt < 2; nt++)
#pragma unroll
                for (int r = 0; r < 4; r++) { dh[nt][r] = 0.f; dl[nt][r] = 0.f; }
#pragma unroll
            for (int ks = 0; ks < 8; ks++) {
                uint32_t ahi0, ahi1, ahi2, ahi3, alo0, alo1, alo2, alo3;
                uint32_t roff = (mt * 16 + (lane & 15)) * HS_STRIDE
                              + ks * 32 + (lane & 16);
                LDSM_X4(ahi0, ahi1, ahi2, ahi3, hshi_base + roff);
                LDSM_X4(alo0, alo1, alo2, alo3, hslo_base + roff);
#pragma unroll
                for (int nt = 0; nt < 2; nt++) {
                    MMA16816(dh[nt][0], dh[nt][1], dh[nt][2], dh[nt][3],
                             ahi0, ahi1, ahi2, ahi3, bhi[ks][nt][0], bhi[ks][nt][1]);
                    MMA16816(dl[nt][0], dl[nt][1], dl[nt][2], dl[nt][3],
                             alo0, alo1, alo2, alo3, bhi[ks][nt][0], bhi[ks][nt][1]);
                    MMA16816(dl[nt][0], dl[nt][1], dl[nt][2], dl[nt][3],
                             ahi0, ahi1, ahi2, ahi3, blo[ks][nt][0], blo[ks][nt][1]);
                }
            }
            const int r0 = rbase + mt * 16 + g;
            const int r1 = r0 + 8;
#pragma unroll
            for (int nt = 0; nt < 2; nt++) {
                int c = n0w + nt * 8 + tig * 2;
                float s0 = dh[nt][0] + dl[nt][0];
                float s1 = dh[nt][1] + dl[nt][1];
                float s2 = dh[nt][2] + dl[nt][2];
                float s3 = dh[nt][3] + dl[nt][3];
                if (c < HH) {
                    float2 v0 = make_float2(s0 + bcn_s[c], s1 + bcn_s[c + 1]);
                    float2 v1 = make_float2(s2 + bcn_s[c], s3 + bcn_s[c + 1]);
                    if (r0 < NN) *(float2*)&g_a[r0 * HH + c] = v0;
                    if (r1 < NN) *(float2*)&g_a[r1 * HH + c] = v1;
                } else {
                    unsigned p0, p1;
                    asm("cvt.rn.bf16x2.f32 %0, %1, %2;" : "=r"(p0) : "f"(s1), "f"(s0));
                    asm("cvt.rn.bf16x2.f32 %0, %1, %2;" : "=r"(p1) : "f"(s3), "f"(s2));
                    int cb = (c - HH) >> 1;
                    if (r0 < NN) g_bh[r0 * 64 + cb] = p0;
                    if (r1 < NN) g_bh[r1 * 64 + cb] = p1;
                }
            }
        }
        CP_WAIT0();
        __syncthreads();   // yraw(t+1) ready; hs free for overwrite
    }
}

// ---------------- K3: TWO warps per node (edges split) -> pool ---------------
__device__ __forceinline__ void red_add_v4(float* p, float4 v) {
    asm volatile("red.global.add.v4.f32 [%0], {%1, %2, %3, %4};"
                 :: "l"(p), "f"(v.x), "f"(v.y), "f"(v.z), "f"(v.w) : "memory");
}

__device__ __forceinline__ void acc_edge(float4& acc, const float4& a, uint2 rb) {
    float b0 = __int_as_float(rb.x << 16);
    float b1 = __int_as_float(rb.x & 0xffff0000u);
    float b2 = __int_as_float(rb.y << 16);
    float b3 = __int_as_float(rb.y & 0xffff0000u);
    acc.x += fmaxf(a.x + b0, 0.f);
    acc.y += fmaxf(a.y + b1, 0.f);
    acc.z += fmaxf(a.z + b2, 0.f);
    acc.w += fmaxf(a.w + b3, 0.f);
}

__global__ void __launch_bounds__(256) k3(const int* __restrict__ seg) {
    const int gw = (blockIdx.x * 256 + threadIdx.x) >> 5;
    const int i = gw >> 1;
    if (i >= NN) return;
    const int half = gw & 1;
    const int lane = threadIdx.x & 31;
    const int deg = min(g_cnt[i], PAD);
    const int e0 = half ? (deg >> 1) : 0;
    const int e1 = half ? deg : (deg >> 1);
    if (e0 >= e1) return;
    const float4 a = *(const float4*)&g_a[i * HH + lane * 4];
    const int g = __ldg(seg + i);
    const int* al = g_adj + i * PAD;
    float4 acc = make_float4(0.f, 0.f, 0.f, 0.f);
    int j = e0;
    for (; j + 8 <= e1; j += 8) {
        int d[8];
#pragma unroll
        for (int u = 0; u < 8; u++) d[u] = __ldg(al + j + u);
        uint2 rb[8];
#pragma unroll
        for (int u = 0; u < 8; u++)
            rb[u] = *(const uint2*)&g_bh[d[u] * 64 + lane * 2];
#pragma unroll
        for (int u = 0; u < 8; u++) acc_edge(acc, a, rb[u]);
    }
    for (; j < e1; j++) {
        int d = __ldg(al + j);
        uint2 rb = *(const uint2*)&g_bh[d * 64 + lane * 2];
        acc_edge(acc, a, rb);
    }
    red_add_v4(&g_p[g * HH + lane * 4], acc);
}

// ---------------- K4: y2 = p @ w_post + b_post ; double col sums -------------
__global__ void __launch_bounds__(128) k4(const float* __restrict__ wpost,
                                          const float* __restrict__ bpost) {
    extern __shared__ float ws4[];
    __shared__ float ps[HH];
    const int t = threadIdx.x;
    for (int i = t; i < HH * HH; i += 128) ws4[i] = wpost[i];
    const float bc = bpost[t];
    const int r0 = blockIdx.x * (GG / 128);
    double bsum = 0.0, bsq = 0.0;
    __syncthreads();
    for (int r = r0; r < r0 + GG / 128; r++) {
        __syncthreads();
        ps[t] = g_p[r * HH + t];
        __syncthreads();
        float A0 = 0.f, A1 = 0.f, A2 = 0.f, A3 = 0.f;
#pragma unroll 8
        for (int k = 0; k < HH; k += 4) {
            A0 = fmaf(ps[k + 0], ws4[(k + 0) * HH + t], A0);
            A1 = fmaf(ps[k + 1], ws4[(k + 1) * HH + t], A1);
            A2 = fmaf(ps[k + 2], ws4[(k + 2) * HH + t], A2);
            A3 = fmaf(ps[k + 3], ws4[(k + 3) * HH + t], A3);
        }
        float acc = ((A0 + A1) + (A2 + A3)) + bc;
        g_y2[r * HH + t] = acc;
        bsum += (double)acc;
        bsq = fma((double)acc, (double)acc, bsq);
    }
    atomicAdd(&g_sum2[t], bsum);
    atomicAdd(&g_sumsq2[t], bsq);
}

// ---------------- K5: relu(BN(y2)) @ w_out + b_out -> sigmoid ----------------
__global__ void __launch_bounds__(256) k5(const float* __restrict__ gpost,
                                          const float* __restrict__ bepost,
                                          const float* __restrict__ wout,
                                          const float* __restrict__ bout,
                                          float* __restrict__ out) {
    const int r = (blockIdx.x * 256 + threadIdx.x) >> 5;
    const int lane = threadIdx.x & 31;
    if (r >= GG) return;
    float acc = 0.f;
#pragma unroll
    for (int j = 0; j < 4; j++) {
        int c = lane + 32 * j;
        double mu = g_sum2[c] * (1.0 / GG);
        float var = (float)(g_sumsq2[c] * (1.0 / GG) - mu * mu);
        float sc = gpost[c] * rsqrtf(var + BN_EPSF);
        float hb = bepost[c] - (float)mu * sc;
        float hn = fmaxf(fmaf(g_y2[r * HH + c], sc, hb), 0.f);
        acc += hn * wout[c];
    }
#pragma unroll
    for (int o = 16; o; o >>= 1) acc += __shfl_down_sync(0xffffffffu, acc, o);
    if (lane == 0) out[r] = 1.f / (1.f + expf(-(acc + bout[0])));
}

// ---------------- launch -----------------------------------------------------
extern "C" void kernel_launch(void* const* d_in, const int* in_sizes, int n_in,
                              void* d_out, int out_size) {
    const float* x      = (const float*)d_in[0];
    const int*   src    = (const int*)d_in[1];
    const int*   dst    = (const int*)d_in[2];
    const int*   seg    = (const int*)d_in[3];
    const float* w_pre  = (const float*)d_in[4];
    const float* b_pre  = (const float*)d_in[5];
    const float* gm_pre = (const float*)d_in[6];
    const float* be_pre = (const float*)d_in[7];
    const float* w_cn   = (const float*)d_in[8];
    const float* b_cn   = (const float*)d_in[9];
    const float* w_post = (const float*)d_in[10];
    const float* b_post = (const float*)d_in[11];
    const float* gm_post= (const float*)d_in[12];
    const float* be_post= (const float*)d_in[13];
    const float* w_out  = (const float*)d_in[14];
    const float* b_out  = (const float*)d_in[15];
    float* out = (float*)d_out;
    const int E = in_sizes[1];

    static cudaStream_t s2 = nullptr;
    static cudaEvent_t ev_fork = nullptr, ev_join = nullptr;
    if (!s2) {
        cudaStreamCreateWithFlags(&s2, cudaStreamNonBlocking);
        cudaEventCreateWithFlags(&ev_fork, cudaEventDisableTiming);
        cudaEventCreateWithFlags(&ev_join, cudaEventDisableTiming);
    }

    const int k4_smem = HH * HH * 4;
    cudaFuncSetAttribute(k2m, cudaFuncAttributeMaxDynamicSharedMemorySize, K2M_SMEM);
    cudaFuncSetAttribute(k4, cudaFuncAttributeMaxDynamicSharedMemorySize, k4_smem);

    // #1: zero everything
    kzero<<<(GG * HH + 255) / 256, 256>>>();
    // fork: adjacency build on s2, concurrent with k1+k2m on main stream
    cudaEventRecord(ev_fork, 0);
    cudaStreamWaitEvent(s2, ev_fork, 0);
    kscat2<<<(E / 8 + 255) / 256, 256, 0, s2>>>(src, dst, E);   // #2
    cudaEventRecord(ev_join, s2);
    // main stream: node GEMMs
    k1<<<(NN + K1_ROWS - 1) / K1_ROWS, 128>>>(x, w_pre, b_pre); // #3
    k2m<<<148, 512, K2M_SMEM>>>(w_cn, b_cn, gm_pre, be_pre);    // #4 (profiled)
    // join: k3 needs adjacency + A/B
    cudaStreamWaitEvent(0, ev_join, 0);
    k3<<<(NN * 2 * 32 + 255) / 256, 256>>>(seg);                // #5
    k4<<<128, 128, k4_smem>>>(w_post, b_post);                  // #6
    k5<<<(GG * 32) / 256, 256>>>(gm_post, be_post, w_out, b_out, out);
}